// round 9
// baseline (speedup 1.0000x reference)
#include <cuda_runtime.h>
#include <cuda_bf16.h>
#include <math.h>
#include <stdint.h>

// ---------------- static scratch ----------------
static __device__ int8_t g_w8[4096u * 4096u];     // q - 128 (exact int8)
static __device__ int8_t g_x1[10240u * 4096u];    // slice 1 of x
static __device__ int8_t g_x2[10240u * 4096u];    // slice 2 of x
static __device__ float  g_delta[10240];          // per-row scale
static __device__ float  g_rsum[10240];           // per-row delta*(R1 + R2/128)
static __device__ float  g_out[10240u * 4096u];   // pre-quant GEMM output
__device__ unsigned g_wmm[2];
__device__ unsigned g_cmin[32], g_cmax[32];
__device__ float g_s3[32], g_z3[32];
__device__ float g_sw, g_zw;

// ---- monotone float <-> uint encoding ----
__device__ __forceinline__ unsigned f2o(float f) {
    unsigned u = __float_as_uint(f);
    return (u & 0x80000000u) ? ~u : (u | 0x80000000u);
}
__device__ __forceinline__ float o2f(unsigned u) {
    unsigned v = (u & 0x80000000u) ? (u ^ 0x80000000u) : ~u;
    return __uint_as_float(v);
}
__device__ __forceinline__ float fq(float v, float s, float z) {
    float q = rintf(__fadd_rn(__fdiv_rn(v, s), z));
    q = fminf(fmaxf(q, 0.0f), 255.0f);
    return __fmul_rn(__fsub_rn(q, z), s);
}

// ---------------- PTX helpers ----------------
__device__ __forceinline__ uint32_t smem_u32(const void* p) {
    uint32_t a;
    asm("{ .reg .u64 t; cvta.to.shared.u64 t, %1; cvt.u32.u64 %0, t; }" : "=r"(a) : "l"(p));
    return a;
}
__device__ __forceinline__ void cpa16(uint32_t d, const void* s) {
    asm volatile("cp.async.cg.shared.global [%0], [%1], 16;" :: "r"(d), "l"(s));
}
__device__ __forceinline__ void cpa_commit() { asm volatile("cp.async.commit_group;" ::: "memory"); }
template<int N> __device__ __forceinline__ void cpa_wait() {
    asm volatile("cp.async.wait_group %0;" :: "n"(N) : "memory");
}
__device__ __forceinline__ void ldsm_x4(uint32_t& r0, uint32_t& r1, uint32_t& r2, uint32_t& r3,
                                        uint32_t addr) {
    asm volatile("ldmatrix.sync.aligned.m8n8.x4.shared.b16 {%0,%1,%2,%3}, [%4];"
                 : "=r"(r0), "=r"(r1), "=r"(r2), "=r"(r3) : "r"(addr));
}
__device__ __forceinline__ void mma_s8(int* c, const uint32_t* a, const uint32_t* b) {
    asm volatile("mma.sync.aligned.m16n8k32.row.col.s32.s8.s8.s32 "
                 "{%0,%1,%2,%3}, {%4,%5,%6,%7}, {%8,%9}, {%0,%1,%2,%3};"
                 : "+r"(c[0]), "+r"(c[1]), "+r"(c[2]), "+r"(c[3])
                 : "r"(a[0]), "r"(a[1]), "r"(a[2]), "r"(a[3]), "r"(b[0]), "r"(b[1]));
}

// ---------------- kernel 0: reset reduction state ----------------
__global__ void init_kernel() {
    if (threadIdx.x == 0) { g_wmm[0] = 0xFFFFFFFFu; g_wmm[1] = 0u; }
    if (threadIdx.x < 32) { g_cmin[threadIdx.x] = 0xFFFFFFFFu; g_cmax[threadIdx.x] = 0u; }
}

// ---------------- kernel 1: weight min/max ----------------
__global__ void wminmax_kernel(const float4* __restrict__ w4, int n4) {
    float mn = INFINITY, mx = -INFINITY;
    for (int i = blockIdx.x * blockDim.x + threadIdx.x; i < n4; i += gridDim.x * blockDim.x) {
        float4 v = w4[i];
        mn = fminf(mn, fminf(fminf(v.x, v.y), fminf(v.z, v.w)));
        mx = fmaxf(mx, fmaxf(fmaxf(v.x, v.y), fmaxf(v.z, v.w)));
    }
    #pragma unroll
    for (int o = 16; o; o >>= 1) {
        mn = fminf(mn, __shfl_xor_sync(0xffffffffu, mn, o));
        mx = fmaxf(mx, __shfl_xor_sync(0xffffffffu, mx, o));
    }
    __shared__ float smn[8], smx[8];
    if ((threadIdx.x & 31) == 0) { smn[threadIdx.x >> 5] = mn; smx[threadIdx.x >> 5] = mx; }
    __syncthreads();
    if (threadIdx.x == 0) {
        for (int i = 1; i < (int)(blockDim.x >> 5); i++) { mn = fminf(mn, smn[i]); mx = fmaxf(mx, smx[i]); }
        atomicMin(&g_wmm[0], f2o(mn));
        atomicMax(&g_wmm[1], f2o(mx));
    }
}

// ---------------- kernel 2: w8 = clamp(round(w/s+z)) - 128 into int8 (exact) ----------------
__global__ void quantw_kernel(const float4* __restrict__ w4, int n4) {
    float mn = o2f(g_wmm[0]), mx = o2f(g_wmm[1]);
    float s = __fdiv_rn(__fsub_rn(mx, mn), 255.0f);
    float z = -rintf(__fdiv_rn(mn, s));
    if (blockIdx.x == 0 && threadIdx.x == 0) { g_sw = s; g_zw = z; }
    uint32_t* dst = reinterpret_cast<uint32_t*>(g_w8);
    for (int i = blockIdx.x * blockDim.x + threadIdx.x; i < n4; i += gridDim.x * blockDim.x) {
        float4 v = w4[i];
        int q0 = (int)fminf(fmaxf(rintf(__fadd_rn(__fdiv_rn(v.x, s), z)), 0.f), 255.f) - 128;
        int q1 = (int)fminf(fmaxf(rintf(__fadd_rn(__fdiv_rn(v.y, s), z)), 0.f), 255.f) - 128;
        int q2 = (int)fminf(fmaxf(rintf(__fadd_rn(__fdiv_rn(v.z, s), z)), 0.f), 255.f) - 128;
        int q3 = (int)fminf(fmaxf(rintf(__fadd_rn(__fdiv_rn(v.w, s), z)), 0.f), 255.f) - 128;
        dst[i] = (uint32_t)(q0 & 255) | ((uint32_t)(q1 & 255) << 8) |
                 ((uint32_t)(q2 & 255) << 16) | ((uint32_t)(q3 & 255) << 24);
    }
}

// ---------------- kernel 3: split x rows into 2 int8 slices (one block per row) ----------------
__global__ __launch_bounds__(256) void splitx_kernel(const float4* __restrict__ x4, int IN) {
    const int row = blockIdx.x;
    const int t = threadIdx.x;
    const int n4row = IN / 4;                 // 1024
    const float4* src = x4 + (size_t)row * n4row;
    float4 v[4];
    float amax = 0.0f;
    #pragma unroll
    for (int j = 0; j < 4; j++) {
        v[j] = __ldg(src + j * 256 + t);
        amax = fmaxf(amax, fmaxf(fmaxf(fabsf(v[j].x), fabsf(v[j].y)),
                                 fmaxf(fabsf(v[j].z), fabsf(v[j].w))));
    }
    // block max
    #pragma unroll
    for (int o = 16; o; o >>= 1) amax = fmaxf(amax, __shfl_xor_sync(0xffffffffu, amax, o));
    __shared__ float smax[8];
    if ((t & 31) == 0) smax[t >> 5] = amax;
    __syncthreads();
    __shared__ float sdelta;
    if (t == 0) {
        float m = smax[0];
        for (int i = 1; i < 8; i++) m = fmaxf(m, smax[i]);
        sdelta = (m > 0.0f) ? (m / 127.0f) : 1.0f;
    }
    __syncthreads();
    const float delta = sdelta;
    const float inv_d = 1.0f / delta;
    const float inv_d2 = 128.0f / delta;

    uint32_t* p1 = reinterpret_cast<uint32_t*>(g_x1) + (size_t)row * n4row;
    uint32_t* p2 = reinterpret_cast<uint32_t*>(g_x2) + (size_t)row * n4row;
    int R1 = 0, R2 = 0;
    #pragma unroll
    for (int j = 0; j < 4; j++) {
        float e[4] = {v[j].x, v[j].y, v[j].z, v[j].w};
        uint32_t w1 = 0, w2 = 0;
        #pragma unroll
        for (int q = 0; q < 4; q++) {
            int a = (int)rintf(e[q] * inv_d);
            float r = e[q] - delta * (float)a;
            int b = (int)rintf(r * inv_d2);
            R1 += a; R2 += b;
            w1 |= (uint32_t)(a & 255) << (8 * q);
            w2 |= (uint32_t)(b & 255) << (8 * q);
        }
        p1[j * 256 + t] = w1;
        p2[j * 256 + t] = w2;
    }
    // block sum R1, R2
    #pragma unroll
    for (int o = 16; o; o >>= 1) {
        R1 += __shfl_xor_sync(0xffffffffu, R1, o);
        R2 += __shfl_xor_sync(0xffffffffu, R2, o);
    }
    __shared__ int s1[8], s2[8];
    if ((t & 31) == 0) { s1[t >> 5] = R1; s2[t >> 5] = R2; }
    __syncthreads();
    if (t == 0) {
        int a = 0, b = 0;
        for (int i = 0; i < 8; i++) { a += s1[i]; b += s2[i]; }
        g_delta[row] = delta;
        g_rsum[row] = delta * ((float)a + (float)b * 0.0078125f);
    }
}

// ---------------- kernel 4: IMMA GEMM ----------------
// out = s*delta_r*(S1 + S2/128) + s*(128-z)*rsum_r + bias
// CTA 128x128, 512 threads, 16 warps 4m x 4n, warp tile 32x32, BK=32, 4-stage cp.async.
#define BM 128
#define BN 128
#define BK 32
#define PITCH 48                        // bytes per smem row (conflict-free for ldmatrix)
#define MAT_BYTES (128 * PITCH)         // 6144 B per matrix
#define STAGE_BYTES (3 * MAT_BYTES)     // x1, x2, w8 = 18432 B
#define NSTAGE 4

__global__ __launch_bounds__(512, 1)
void gemm_imma(const float* __restrict__ bias, int IN, int OUT, int nPer) {
    extern __shared__ char dsm[];
    const uint32_t sb = smem_u32(dsm);
    const int t = threadIdx.x;
    const int wid = t >> 5;
    const int lane = t & 31;
    const int wm = wid & 3;             // 4 m-warps
    const int wn = wid >> 2;            // 4 n-warps
    const int mwarp = wm * 32;
    const int nwarp = wn * 32;
    const int rowbase = blockIdx.y * BM;
    const int colbase = blockIdx.x * BN;
    const int NITER = IN / BK;

    const int8_t* x1p = g_x1;
    const int8_t* x2p = g_x2;
    const int8_t* w8p = g_w8;

    // stage loader: 768 x 16B chunks (x1 256, x2 256, w8 256)
    auto load_stage = [&](int s, int it) {
        const int k0 = it * BK;
        const uint32_t st = sb + s * STAGE_BYTES;
        #pragma unroll
        for (int j = 0; j < 2; j++) {
            const int ci = j * 512 + t;
            if (ci < 768) {
                const int m = ci >> 8;            // 0: x1, 1: x2, 2: w8
                const int r = (ci & 255) >> 1;    // 0..127
                const int c = ci & 1;             // 16B half
                uint32_t dst = st + (uint32_t)(m * MAT_BYTES + r * PITCH + c * 16);
                const int8_t* src;
                if (m == 0)      src = x1p + (size_t)(rowbase + r) * IN + k0 + c * 16;
                else if (m == 1) src = x2p + (size_t)(rowbase + r) * IN + k0 + c * 16;
                else             src = w8p + (size_t)(colbase + r) * IN + k0 + c * 16;
                cpa16(dst, src);
            }
        }
    };

    // ldmatrix per-thread address components (int8, 16B halves)
    const int rowA = lane & 15;                           // rows 0..15
    const int kcolA = (lane >> 4) << 4;                   // byte 0 or 16
    const int rowB = (lane & 7) + ((lane >> 4) & 1) * 8;  // n row within 16
    const int kcolB = ((lane >> 3) & 1) << 4;             // byte 0 or 16

    int acc1[2][4][4], acc2[2][4][4];
    #pragma unroll
    for (int i = 0; i < 2; i++)
        #pragma unroll
        for (int j = 0; j < 4; j++)
            #pragma unroll
            for (int e = 0; e < 4; e++) { acc1[i][j][e] = 0; acc2[i][j][e] = 0; }

    load_stage(0, 0); cpa_commit();
    load_stage(1, 1); cpa_commit();
    load_stage(2, 2); cpa_commit();

    for (int it = 0; it < NITER; ++it) {
        const int s = it & 3;
        cpa_wait<2>();
        __syncthreads();
        if (it + 3 < NITER) load_stage((it + 3) & 3, it + 3);
        cpa_commit();

        const uint32_t st = sb + s * STAGE_BYTES;
        // B: 4 n8-tiles (n32 x k32) via 2 ldmatrix.x4 — shared by both slices
        uint32_t b[4][2];
        #pragma unroll
        for (int np = 0; np < 2; np++) {
            uint32_t addr = st + 2 * MAT_BYTES +
                (uint32_t)((nwarp + np * 16 + rowB) * PITCH + kcolB);
            ldsm_x4(b[2 * np][0], b[2 * np][1], b[2 * np + 1][0], b[2 * np + 1][1], addr);
        }
        uint32_t a[2][4];
        // slice 1
        #pragma unroll
        for (int mt = 0; mt < 2; mt++) {
            uint32_t addr = st + (uint32_t)((mwarp + mt * 16 + rowA) * PITCH + kcolA);
            ldsm_x4(a[mt][0], a[mt][1], a[mt][2], a[mt][3], addr);
        }
        #pragma unroll
        for (int mt = 0; mt < 2; mt++)
            #pragma unroll
            for (int nt = 0; nt < 4; nt++) mma_s8(acc1[mt][nt], a[mt], b[nt]);
        // slice 2
        #pragma unroll
        for (int mt = 0; mt < 2; mt++) {
            uint32_t addr = st + MAT_BYTES + (uint32_t)((mwarp + mt * 16 + rowA) * PITCH + kcolA);
            ldsm_x4(a[mt][0], a[mt][1], a[mt][2], a[mt][3], addr);
        }
        #pragma unroll
        for (int mt = 0; mt < 2; mt++)
            #pragma unroll
            for (int nt = 0; nt < 4; nt++) mma_s8(acc2[mt][nt], a[mt], b[nt]);
    }

    // ---------------- epilogue ----------------
    const float s_w = g_sw;
    const float szf = s_w * (128.0f - g_zw);
    float lmn = INFINITY, lmx = -INFINITY;

    float2 bv[4];
    #pragma unroll
    for (int nt = 0; nt < 4; nt++)
        bv[nt] = *reinterpret_cast<const float2*>(bias + colbase + nwarp + nt * 8 + (lane & 3) * 2);

    #pragma unroll
    for (int mt = 0; mt < 2; mt++) {
        #pragma unroll
        for (int half = 0; half < 2; half++) {
            const int grow = rowbase + mwarp + mt * 16 + (lane >> 2) + half * 8;
            const float sd = s_w * __ldg(&g_delta[grow]);
            const float cr = szf * __ldg(&g_rsum[grow]);
            float* dstrow = g_out + (size_t)grow * OUT + colbase + nwarp + (lane & 3) * 2;
            #pragma unroll
            for (int nt = 0; nt < 4; nt++) {
                float f0 = fmaf((float)acc2[mt][nt][half * 2 + 0], 0.0078125f,
                                (float)acc1[mt][nt][half * 2 + 0]);
                float f1 = fmaf((float)acc2[mt][nt][half * 2 + 1], 0.0078125f,
                                (float)acc1[mt][nt][half * 2 + 1]);
                float v0 = fmaf(sd, f0, cr + bv[nt].x);
                float v1 = fmaf(sd, f1, cr + bv[nt].y);
                lmn = fminf(lmn, fminf(v0, v1));
                lmx = fmaxf(lmx, fmaxf(v0, v1));
                *reinterpret_cast<float2*>(dstrow + nt * 8) = make_float2(v0, v1);
            }
        }
    }

    #pragma unroll
    for (int o = 16; o; o >>= 1) {
        lmn = fminf(lmn, __shfl_xor_sync(0xffffffffu, lmn, o));
        lmx = fmaxf(lmx, __shfl_xor_sync(0xffffffffu, lmx, o));
    }
    __shared__ float rmn[16], rmx[16];
    if (lane == 0) { rmn[wid] = lmn; rmx[wid] = lmx; }
    __syncthreads();
    if (t == 0) {
        for (int i = 1; i < 16; i++) { lmn = fminf(lmn, rmn[i]); lmx = fmaxf(lmx, rmx[i]); }
        int cl = rowbase / nPer;
        atomicMin(&g_cmin[cl], f2o(lmn));
        atomicMax(&g_cmax[cl], f2o(lmx));
    }
}

// ---------------- kernel 5: EMA range update + qparams ----------------
__global__ void range_kernel(const float* __restrict__ act_range, const int* __restrict__ cinfo,
                             float* __restrict__ out_range, int K) {
    int t = threadIdx.x;
    if (t < K) {
        out_range[2 * t]     = act_range[2 * t];
        out_range[2 * t + 1] = act_range[2 * t + 1];
    }
    __syncthreads();
    if (t < K) {
        float mn = o2f(g_cmin[t]), mx = o2f(g_cmax[t]);
        int c = cinfo[2 * t];
        float o0 = act_range[2 * c], o1 = act_range[2 * c + 1];
        float nmin = __fadd_rn(__fmul_rn(o0, 0.999f), __fmul_rn(mn, 0.001f));
        float nmax = __fadd_rn(__fmul_rn(o1, 0.999f), __fmul_rn(mx, 0.001f));
        out_range[2 * c]     = nmin;
        out_range[2 * c + 1] = nmax;
        float s = __fdiv_rn(__fsub_rn(nmax, nmin), 255.0f);
        g_s3[t] = s;
        g_z3[t] = -rintf(__fdiv_rn(nmin, s));
    }
}

// ---------------- kernel 6: fake-quantize GEMM output ----------------
__global__ void quantout_kernel(float4* __restrict__ outq, int n4, int chunk4) {
    const float4* src = reinterpret_cast<const float4*>(g_out);
    for (int i = blockIdx.x * blockDim.x + threadIdx.x; i < n4; i += gridDim.x * blockDim.x) {
        int k = i / chunk4;
        float s = g_s3[k], z = g_z3[k];
        float4 v = src[i];
        v.x = fq(v.x, s, z); v.y = fq(v.y, s, z);
        v.z = fq(v.z, s, z); v.w = fq(v.w, s, z);
        outq[i] = v;
    }
}

// ---------------- launch ----------------
extern "C" void kernel_launch(void* const* d_in, const int* in_sizes, int n_in,
                              void* d_out, int out_size) {
    const float* x         = (const float*)d_in[0];
    const float* w         = (const float*)d_in[1];
    const float* bias      = (const float*)d_in[2];
    const float* act_range = (const float*)d_in[3];
    const int*   cinfo     = (const int*)d_in[4];

    const int OUT = in_sizes[2];
    const int IN  = in_sizes[1] / OUT;
    const int B   = in_sizes[0] / IN;
    const int K   = in_sizes[3] / 2;
    const int n   = B / K;

    float* outq      = (float*)d_out;
    float* out_range = outq + (size_t)B * OUT;

    const int smem_bytes = NSTAGE * STAGE_BYTES;   // 73728
    cudaFuncSetAttribute(gemm_imma, cudaFuncAttributeMaxDynamicSharedMemorySize, smem_bytes);

    init_kernel<<<1, 32>>>();

    const int wn4 = (OUT * IN) / 4;
    wminmax_kernel<<<512, 256>>>((const float4*)w, wn4);
    quantw_kernel<<<2048, 256>>>((const float4*)w, wn4);

    splitx_kernel<<<B, 256>>>((const float4*)x, IN);

    dim3 grid(OUT / BN, B / BM);
    gemm_imma<<<grid, 512, smem_bytes>>>(bias, IN, OUT, n);

    range_kernel<<<1, 32>>>(act_range, cinfo, out_range, K);

    const int on4 = (B / 4) * OUT;
    quantout_kernel<<<2048, 256>>>((float4*)outq, on4, (n * OUT) / 4);
}

// round 10
// speedup vs baseline: 2.4983x; 2.4983x over previous
#include <cuda_runtime.h>
#include <cuda_bf16.h>
#include <math.h>
#include <stdint.h>

// ---------------- static scratch ----------------
static __device__ __nv_bfloat16 g_wqb[4096u * 4096u];   // W' = q - z (exact ints in bf16)
static __device__ __nv_bfloat16 g_xhi[10240u * 4096u];  // bf16 hi part of x
static __device__ __nv_bfloat16 g_xlo[10240u * 4096u];  // bf16 lo residual of x
static __device__ float g_out[10240u * 4096u];          // pre-quant GEMM output
__device__ unsigned g_wmm[2];
__device__ unsigned g_cmin[32], g_cmax[32];
__device__ float g_s3[32], g_z3[32];
__device__ float g_sw;

// ---- monotone float <-> uint encoding ----
__device__ __forceinline__ unsigned f2o(float f) {
    unsigned u = __float_as_uint(f);
    return (u & 0x80000000u) ? ~u : (u | 0x80000000u);
}
__device__ __forceinline__ float o2f(unsigned u) {
    unsigned v = (u & 0x80000000u) ? (u ^ 0x80000000u) : ~u;
    return __uint_as_float(v);
}
__device__ __forceinline__ float fq(float v, float s, float z) {
    float q = rintf(__fadd_rn(__fdiv_rn(v, s), z));
    q = fminf(fmaxf(q, 0.0f), 255.0f);
    return __fmul_rn(__fsub_rn(q, z), s);
}

// ---------------- PTX helpers ----------------
__device__ __forceinline__ uint32_t smem_u32(const void* p) {
    uint32_t a;
    asm("{ .reg .u64 t; cvta.to.shared.u64 t, %1; cvt.u32.u64 %0, t; }" : "=r"(a) : "l"(p));
    return a;
}
__device__ __forceinline__ void cpa16(uint32_t d, const void* s) {
    asm volatile("cp.async.cg.shared.global [%0], [%1], 16;" :: "r"(d), "l"(s));
}
__device__ __forceinline__ void cpa_commit() { asm volatile("cp.async.commit_group;" ::: "memory"); }
template<int N> __device__ __forceinline__ void cpa_wait() {
    asm volatile("cp.async.wait_group %0;" :: "n"(N) : "memory");
}
__device__ __forceinline__ void ldsm_x4(uint32_t& r0, uint32_t& r1, uint32_t& r2, uint32_t& r3,
                                        uint32_t addr) {
    asm volatile("ldmatrix.sync.aligned.m8n8.x4.shared.b16 {%0,%1,%2,%3}, [%4];"
                 : "=r"(r0), "=r"(r1), "=r"(r2), "=r"(r3) : "r"(addr));
}
__device__ __forceinline__ void mma16816(float* c, const uint32_t* a, const uint32_t* b) {
    asm volatile("mma.sync.aligned.m16n8k16.row.col.f32.bf16.bf16.f32 "
                 "{%0,%1,%2,%3}, {%4,%5,%6,%7}, {%8,%9}, {%0,%1,%2,%3};"
                 : "+f"(c[0]), "+f"(c[1]), "+f"(c[2]), "+f"(c[3])
                 : "r"(a[0]), "r"(a[1]), "r"(a[2]), "r"(a[3]), "r"(b[0]), "r"(b[1]));
}

// ---------------- kernel 0: reset reduction state ----------------
__global__ void init_kernel() {
    if (threadIdx.x == 0) { g_wmm[0] = 0xFFFFFFFFu; g_wmm[1] = 0u; }
    if (threadIdx.x < 32) { g_cmin[threadIdx.x] = 0xFFFFFFFFu; g_cmax[threadIdx.x] = 0u; }
}

// ---------------- kernel 1: weight min/max ----------------
__global__ void wminmax_kernel(const float4* __restrict__ w4, int n4) {
    float mn = INFINITY, mx = -INFINITY;
    for (int i = blockIdx.x * blockDim.x + threadIdx.x; i < n4; i += gridDim.x * blockDim.x) {
        float4 v = w4[i];
        mn = fminf(mn, fminf(fminf(v.x, v.y), fminf(v.z, v.w)));
        mx = fmaxf(mx, fmaxf(fmaxf(v.x, v.y), fmaxf(v.z, v.w)));
    }
    #pragma unroll
    for (int o = 16; o; o >>= 1) {
        mn = fminf(mn, __shfl_xor_sync(0xffffffffu, mn, o));
        mx = fmaxf(mx, __shfl_xor_sync(0xffffffffu, mx, o));
    }
    __shared__ float smn[8], smx[8];
    if ((threadIdx.x & 31) == 0) { smn[threadIdx.x >> 5] = mn; smx[threadIdx.x >> 5] = mx; }
    __syncthreads();
    if (threadIdx.x == 0) {
        for (int i = 1; i < (int)(blockDim.x >> 5); i++) { mn = fminf(mn, smn[i]); mx = fmaxf(mx, smx[i]); }
        atomicMin(&g_wmm[0], f2o(mn));
        atomicMax(&g_wmm[1], f2o(mx));
    }
}

// ---------------- kernel 2: W' = q - z into bf16 (exact) ----------------
__global__ void quantw_kernel(const float4* __restrict__ w4, int n4) {
    float mn = o2f(g_wmm[0]), mx = o2f(g_wmm[1]);
    float s = __fdiv_rn(__fsub_rn(mx, mn), 255.0f);
    float z = -rintf(__fdiv_rn(mn, s));
    if (blockIdx.x == 0 && threadIdx.x == 0) g_sw = s;
    __nv_bfloat162* dst = reinterpret_cast<__nv_bfloat162*>(g_wqb);
    for (int i = blockIdx.x * blockDim.x + threadIdx.x; i < n4; i += gridDim.x * blockDim.x) {
        float4 v = w4[i];
        float q0 = fminf(fmaxf(rintf(__fadd_rn(__fdiv_rn(v.x, s), z)), 0.f), 255.f) - z;
        float q1 = fminf(fmaxf(rintf(__fadd_rn(__fdiv_rn(v.y, s), z)), 0.f), 255.f) - z;
        float q2 = fminf(fmaxf(rintf(__fadd_rn(__fdiv_rn(v.z, s), z)), 0.f), 255.f) - z;
        float q3 = fminf(fmaxf(rintf(__fadd_rn(__fdiv_rn(v.w, s), z)), 0.f), 255.f) - z;
        __nv_bfloat162 a, b;
        a.x = __float2bfloat16(q0); a.y = __float2bfloat16(q1);
        b.x = __float2bfloat16(q2); b.y = __float2bfloat16(q3);
        dst[2 * i] = a; dst[2 * i + 1] = b;
    }
}

// ---------------- kernel 3: split x into hi/lo bf16 ----------------
__global__ void split_kernel(const float4* __restrict__ x4, int n4) {
    __nv_bfloat162* hi2 = reinterpret_cast<__nv_bfloat162*>(g_xhi);
    __nv_bfloat162* lo2 = reinterpret_cast<__nv_bfloat162*>(g_xlo);
    for (int i = blockIdx.x * blockDim.x + threadIdx.x; i < n4; i += gridDim.x * blockDim.x) {
        float4 v = x4[i];
        __nv_bfloat16 hx = __float2bfloat16(v.x), hy = __float2bfloat16(v.y);
        __nv_bfloat16 hz = __float2bfloat16(v.z), hw = __float2bfloat16(v.w);
        __nv_bfloat162 h01, h23, l01, l23;
        h01.x = hx; h01.y = hy; h23.x = hz; h23.y = hw;
        l01.x = __float2bfloat16(v.x - __bfloat162float(hx));
        l01.y = __float2bfloat16(v.y - __bfloat162float(hy));
        l23.x = __float2bfloat16(v.z - __bfloat162float(hz));
        l23.y = __float2bfloat16(v.w - __bfloat162float(hw));
        hi2[2 * i] = h01; hi2[2 * i + 1] = h23;
        lo2[2 * i] = l01; lo2[2 * i + 1] = l23;
    }
}

// ---------------- kernel 4: HMMA GEMM  out = s_w*(xhi@W'^T + xlo@W'^T) + bias ----------------
// CTA tile 128x128, BK=32, 8 warps (2m x 4n), warp tile 64x32, 3-stage cp.async, 2 CTAs/SM.
#define BM 128
#define BN 128
#define BK 32
#define PITCH 40                      // bf16 elements per smem row (80 B, conflict-free)
#define MAT_BYTES (128 * PITCH * 2)   // 10240 B per matrix
#define STAGE_BYTES (3 * MAT_BYTES)   // A_hi, A_lo, B
#define NSTAGE 3

__global__ __launch_bounds__(256, 2)
void gemm_tc(const float* __restrict__ bias, int IN, int OUT, int nPer) {
    extern __shared__ char dsm[];
    const uint32_t sb = smem_u32(dsm);
    const int t = threadIdx.x;
    const int wid = t >> 5;
    const int lane = t & 31;
    const int wm = wid & 1;           // 2 m-warps
    const int wn = wid >> 1;          // 4 n-warps
    const int mwarp = wm * 64;
    const int nwarp = wn * 32;
    const int rowbase = blockIdx.y * BM;
    const int colbase = blockIdx.x * BN;
    const int NITER = IN / BK;

    const __nv_bfloat16* xhi = g_xhi;
    const __nv_bfloat16* xlo = g_xlo;
    const __nv_bfloat16* wqb = g_wqb;

    // stage loader: 1536 x 16B chunks (A_hi 512, A_lo 512, B 512), 6 per thread
    auto load_stage = [&](int s, int it) {
        const int k0 = it * BK;
        const uint32_t st = sb + s * STAGE_BYTES;
        #pragma unroll
        for (int j = 0; j < 6; j++) {
            const int m = j >> 1;                 // 0: xhi, 1: xlo, 2: W'
            const int ci = ((j & 1) << 8) + t;    // 0..511
            const int r = ci >> 2, c = ci & 3;
            uint32_t dst = st + (uint32_t)(m * MAT_BYTES + r * (PITCH * 2) + c * 16);
            const __nv_bfloat16* src;
            if (m == 0)      src = xhi + (size_t)(rowbase + r) * IN + k0 + c * 8;
            else if (m == 1) src = xlo + (size_t)(rowbase + r) * IN + k0 + c * 8;
            else             src = wqb + (size_t)(colbase + r) * IN + k0 + c * 8;
            cpa16(dst, src);
        }
    };

    // ldmatrix per-thread address components
    const int rowA = lane & 15;                           // row within 16-row tile
    const int kcolA = (lane >> 4) << 3;                   // 0 or 8
    const int rowB = (lane & 7) + ((lane >> 4) & 1) * 8;  // row within 16-row pair of n-tiles
    const int kcolB = ((lane >> 3) & 1) << 3;             // 0 or 8

    float acc[4][4][4];
    #pragma unroll
    for (int i = 0; i < 4; i++)
        #pragma unroll
        for (int j = 0; j < 4; j++)
            #pragma unroll
            for (int e = 0; e < 4; e++) acc[i][j][e] = 0.0f;

    load_stage(0, 0); cpa_commit();
    load_stage(1, 1); cpa_commit();

    for (int it = 0; it < NITER; ++it) {
        const int s = it % NSTAGE;
        cpa_wait<1>();
        __syncthreads();
        if (it + 2 < NITER) load_stage((it + 2) % NSTAGE, it + 2);
        cpa_commit();

        const uint32_t st = sb + s * STAGE_BYTES;
        #pragma unroll
        for (int kk = 0; kk < 2; kk++) {
            const int kb = kk * 16;
            // B: 4 n-tiles via 2 ldmatrix.x4 (2 n-tiles each)
            uint32_t b[4][2];
            #pragma unroll
            for (int np = 0; np < 2; np++) {
                uint32_t addr = st + 2 * MAT_BYTES +
                    (uint32_t)((nwarp + np * 16 + rowB) * (PITCH * 2) + (kb + kcolB) * 2);
                ldsm_x4(b[2 * np][0], b[2 * np][1], b[2 * np + 1][0], b[2 * np + 1][1], addr);
            }
            uint32_t a[4][4];
            // hi
            #pragma unroll
            for (int mt = 0; mt < 4; mt++) {
                uint32_t addr = st +
                    (uint32_t)((mwarp + mt * 16 + rowA) * (PITCH * 2) + (kb + kcolA) * 2);
                ldsm_x4(a[mt][0], a[mt][1], a[mt][2], a[mt][3], addr);
            }
            #pragma unroll
            for (int mt = 0; mt < 4; mt++)
                #pragma unroll
                for (int nt = 0; nt < 4; nt++) mma16816(acc[mt][nt], a[mt], b[nt]);
            // lo
            #pragma unroll
            for (int mt = 0; mt < 4; mt++) {
                uint32_t addr = st + MAT_BYTES +
                    (uint32_t)((mwarp + mt * 16 + rowA) * (PITCH * 2) + (kb + kcolA) * 2);
                ldsm_x4(a[mt][0], a[mt][1], a[mt][2], a[mt][3], addr);
            }
            #pragma unroll
            for (int mt = 0; mt < 4; mt++)
                #pragma unroll
                for (int nt = 0; nt < 4; nt++) mma16816(acc[mt][nt], a[mt], b[nt]);
        }
    }

    // ---------------- epilogue ----------------
    const float s_w = g_sw;
    float lmn = INFINITY, lmx = -INFINITY;

    float2 bv[4];
    #pragma unroll
    for (int nt = 0; nt < 4; nt++)
        bv[nt] = *reinterpret_cast<const float2*>(bias + colbase + nwarp + nt * 8 + (lane & 3) * 2);

    #pragma unroll
    for (int mt = 0; mt < 4; mt++) {
        #pragma unroll
        for (int half = 0; half < 2; half++) {
            const int grow = rowbase + mwarp + mt * 16 + (lane >> 2) + half * 8;
            float* dstrow = g_out + (size_t)grow * OUT + colbase + nwarp + (lane & 3) * 2;
            #pragma unroll
            for (int nt = 0; nt < 4; nt++) {
                float v0 = fmaf(s_w, acc[mt][nt][half * 2 + 0], bv[nt].x);
                float v1 = fmaf(s_w, acc[mt][nt][half * 2 + 1], bv[nt].y);
                lmn = fminf(lmn, fminf(v0, v1));
                lmx = fmaxf(lmx, fmaxf(v0, v1));
                *reinterpret_cast<float2*>(dstrow + nt * 8) = make_float2(v0, v1);
            }
        }
    }

    #pragma unroll
    for (int o = 16; o; o >>= 1) {
        lmn = fminf(lmn, __shfl_xor_sync(0xffffffffu, lmn, o));
        lmx = fmaxf(lmx, __shfl_xor_sync(0xffffffffu, lmx, o));
    }
    __shared__ float rmn[8], rmx[8];
    if (lane == 0) { rmn[wid] = lmn; rmx[wid] = lmx; }
    __syncthreads();
    if (t == 0) {
        for (int i = 1; i < 8; i++) { lmn = fminf(lmn, rmn[i]); lmx = fmaxf(lmx, rmx[i]); }
        int cl = rowbase / nPer;
        atomicMin(&g_cmin[cl], f2o(lmn));
        atomicMax(&g_cmax[cl], f2o(lmx));
    }
}

// ---------------- kernel 5: EMA range update + qparams ----------------
__global__ void range_kernel(const float* __restrict__ act_range, const int* __restrict__ cinfo,
                             float* __restrict__ out_range, int K) {
    int t = threadIdx.x;
    if (t < K) {
        out_range[2 * t]     = act_range[2 * t];
        out_range[2 * t + 1] = act_range[2 * t + 1];
    }
    __syncthreads();
    if (t < K) {
        float mn = o2f(g_cmin[t]), mx = o2f(g_cmax[t]);
        int c = cinfo[2 * t];
        float o0 = act_range[2 * c], o1 = act_range[2 * c + 1];
        float nmin = __fadd_rn(__fmul_rn(o0, 0.999f), __fmul_rn(mn, 0.001f));
        float nmax = __fadd_rn(__fmul_rn(o1, 0.999f), __fmul_rn(mx, 0.001f));
        out_range[2 * c]     = nmin;
        out_range[2 * c + 1] = nmax;
        float s = __fdiv_rn(__fsub_rn(nmax, nmin), 255.0f);
        g_s3[t] = s;
        g_z3[t] = -rintf(__fdiv_rn(nmin, s));
    }
}

// ---------------- kernel 6: fake-quantize GEMM output ----------------
__global__ void quantout_kernel(float4* __restrict__ outq, int n4, int shift) {
    const float4* src = reinterpret_cast<const float4*>(g_out);
    for (int i = blockIdx.x * blockDim.x + threadIdx.x; i < n4; i += gridDim.x * blockDim.x) {
        int k = i >> shift;
        float s = g_s3[k], z = g_z3[k];
        float4 v = src[i];
        v.x = fq(v.x, s, z); v.y = fq(v.y, s, z);
        v.z = fq(v.z, s, z); v.w = fq(v.w, s, z);
        outq[i] = v;
    }
}
// fallback when chunk4 is not a power of two
__global__ void quantout_div_kernel(float4* __restrict__ outq, int n4, int chunk4) {
    const float4* src = reinterpret_cast<const float4*>(g_out);
    for (int i = blockIdx.x * blockDim.x + threadIdx.x; i < n4; i += gridDim.x * blockDim.x) {
        int k = i / chunk4;
        float s = g_s3[k], z = g_z3[k];
        float4 v = src[i];
        v.x = fq(v.x, s, z); v.y = fq(v.y, s, z);
        v.z = fq(v.z, s, z); v.w = fq(v.w, s, z);
        outq[i] = v;
    }
}

// ---------------- launch ----------------
extern "C" void kernel_launch(void* const* d_in, const int* in_sizes, int n_in,
                              void* d_out, int out_size) {
    const float* x         = (const float*)d_in[0];
    const float* w         = (const float*)d_in[1];
    const float* bias      = (const float*)d_in[2];
    const float* act_range = (const float*)d_in[3];
    const int*   cinfo     = (const int*)d_in[4];

    const int OUT = in_sizes[2];
    const int IN  = in_sizes[1] / OUT;
    const int B   = in_sizes[0] / IN;
    const int K   = in_sizes[3] / 2;
    const int n   = B / K;

    float* outq      = (float*)d_out;
    float* out_range = outq + (size_t)B * OUT;

    const int smem_bytes = NSTAGE * STAGE_BYTES;
    cudaFuncSetAttribute(gemm_tc, cudaFuncAttributeMaxDynamicSharedMemorySize, smem_bytes);

    init_kernel<<<1, 32>>>();

    const int wn4 = (OUT * IN) / 4;
    wminmax_kernel<<<512, 256>>>((const float4*)w, wn4);
    quantw_kernel<<<2048, 256>>>((const float4*)w, wn4);

    const int xn4 = (B * IN) / 4;
    split_kernel<<<2048, 256>>>((const float4*)x, xn4);

    dim3 grid(OUT / BN, B / BM);
    gemm_tc<<<grid, 256, smem_bytes>>>(bias, IN, OUT, n);

    range_kernel<<<1, 32>>>(act_range, cinfo, out_range, K);

    const int on4 = (B / 4) * OUT;
    const int chunk4 = (n * OUT) / 4;
    if ((chunk4 & (chunk4 - 1)) == 0) {
        int shift = 0;
        while ((1 << shift) < chunk4) shift++;
        quantout_kernel<<<2048, 256>>>((float4*)outq, on4, shift);
    } else {
        quantout_div_kernel<<<2048, 256>>>((float4*)outq, on4, chunk4);
    }
}

// round 11
// speedup vs baseline: 2.9439x; 1.1783x over previous
#include <cuda_runtime.h>
#include <cuda_bf16.h>
#include <math.h>
#include <stdint.h>

// ---------------- static scratch ----------------
static __device__ __nv_bfloat16 g_wqb[4096u * 4096u];   // W' = q - z (exact ints in bf16)
static __device__ __nv_bfloat16 g_xhi[10240u * 4096u];  // bf16 hi part of x
static __device__ __nv_bfloat16 g_xlo[10240u * 4096u];  // bf16 lo residual of x
static __device__ float g_out[10240u * 4096u];          // pre-quant GEMM output
__device__ unsigned g_wmm[2];
__device__ unsigned g_cmin[32], g_cmax[32];
__device__ float g_s3[32], g_z3[32];
__device__ float g_sw;

// ---- monotone float <-> uint encoding ----
__device__ __forceinline__ unsigned f2o(float f) {
    unsigned u = __float_as_uint(f);
    return (u & 0x80000000u) ? ~u : (u | 0x80000000u);
}
__device__ __forceinline__ float o2f(unsigned u) {
    unsigned v = (u & 0x80000000u) ? (u ^ 0x80000000u) : ~u;
    return __uint_as_float(v);
}
__device__ __forceinline__ float fq(float v, float s, float z) {
    float q = rintf(__fadd_rn(__fdiv_rn(v, s), z));
    q = fminf(fmaxf(q, 0.0f), 255.0f);
    return __fmul_rn(__fsub_rn(q, z), s);
}

// ---------------- PTX helpers ----------------
__device__ __forceinline__ uint32_t smem_u32(const void* p) {
    uint32_t a;
    asm("{ .reg .u64 t; cvta.to.shared.u64 t, %1; cvt.u32.u64 %0, t; }" : "=r"(a) : "l"(p));
    return a;
}
__device__ __forceinline__ void cpa16(uint32_t d, const void* s) {
    asm volatile("cp.async.cg.shared.global [%0], [%1], 16;" :: "r"(d), "l"(s));
}
__device__ __forceinline__ void cpa_commit() { asm volatile("cp.async.commit_group;" ::: "memory"); }
template<int N> __device__ __forceinline__ void cpa_wait() {
    asm volatile("cp.async.wait_group %0;" :: "n"(N) : "memory");
}
__device__ __forceinline__ void ldsm_x4(uint32_t& r0, uint32_t& r1, uint32_t& r2, uint32_t& r3,
                                        uint32_t addr) {
    asm volatile("ldmatrix.sync.aligned.m8n8.x4.shared.b16 {%0,%1,%2,%3}, [%4];"
                 : "=r"(r0), "=r"(r1), "=r"(r2), "=r"(r3) : "r"(addr));
}
__device__ __forceinline__ void mma16816(float* c, const uint32_t* a, const uint32_t* b) {
    asm volatile("mma.sync.aligned.m16n8k16.row.col.f32.bf16.bf16.f32 "
                 "{%0,%1,%2,%3}, {%4,%5,%6,%7}, {%8,%9}, {%0,%1,%2,%3};"
                 : "+f"(c[0]), "+f"(c[1]), "+f"(c[2]), "+f"(c[3])
                 : "r"(a[0]), "r"(a[1]), "r"(a[2]), "r"(a[3]), "r"(b[0]), "r"(b[1]));
}

// ---------------- kernel 0: reset reduction state ----------------
__global__ void init_kernel() {
    if (threadIdx.x == 0) { g_wmm[0] = 0xFFFFFFFFu; g_wmm[1] = 0u; }
    if (threadIdx.x < 32) { g_cmin[threadIdx.x] = 0xFFFFFFFFu; g_cmax[threadIdx.x] = 0u; }
}

// ---------------- kernel 1: weight min/max ----------------
__global__ void wminmax_kernel(const float4* __restrict__ w4, int n4) {
    float mn = INFINITY, mx = -INFINITY;
    for (int i = blockIdx.x * blockDim.x + threadIdx.x; i < n4; i += gridDim.x * blockDim.x) {
        float4 v = w4[i];
        mn = fminf(mn, fminf(fminf(v.x, v.y), fminf(v.z, v.w)));
        mx = fmaxf(mx, fmaxf(fmaxf(v.x, v.y), fmaxf(v.z, v.w)));
    }
    #pragma unroll
    for (int o = 16; o; o >>= 1) {
        mn = fminf(mn, __shfl_xor_sync(0xffffffffu, mn, o));
        mx = fmaxf(mx, __shfl_xor_sync(0xffffffffu, mx, o));
    }
    __shared__ float smn[8], smx[8];
    if ((threadIdx.x & 31) == 0) { smn[threadIdx.x >> 5] = mn; smx[threadIdx.x >> 5] = mx; }
    __syncthreads();
    if (threadIdx.x == 0) {
        for (int i = 1; i < (int)(blockDim.x >> 5); i++) { mn = fminf(mn, smn[i]); mx = fmaxf(mx, smx[i]); }
        atomicMin(&g_wmm[0], f2o(mn));
        atomicMax(&g_wmm[1], f2o(mx));
    }
}

// ---------------- kernel 2: W' = q - z into bf16 (exact) ----------------
__global__ void quantw_kernel(const float4* __restrict__ w4, int n4) {
    float mn = o2f(g_wmm[0]), mx = o2f(g_wmm[1]);
    float s = __fdiv_rn(__fsub_rn(mx, mn), 255.0f);
    float z = -rintf(__fdiv_rn(mn, s));
    if (blockIdx.x == 0 && threadIdx.x == 0) g_sw = s;
    __nv_bfloat162* dst = reinterpret_cast<__nv_bfloat162*>(g_wqb);
    for (int i = blockIdx.x * blockDim.x + threadIdx.x; i < n4; i += gridDim.x * blockDim.x) {
        float4 v = w4[i];
        float q0 = fminf(fmaxf(rintf(__fadd_rn(__fdiv_rn(v.x, s), z)), 0.f), 255.f) - z;
        float q1 = fminf(fmaxf(rintf(__fadd_rn(__fdiv_rn(v.y, s), z)), 0.f), 255.f) - z;
        float q2 = fminf(fmaxf(rintf(__fadd_rn(__fdiv_rn(v.z, s), z)), 0.f), 255.f) - z;
        float q3 = fminf(fmaxf(rintf(__fadd_rn(__fdiv_rn(v.w, s), z)), 0.f), 255.f) - z;
        __nv_bfloat162 a, b;
        a.x = __float2bfloat16(q0); a.y = __float2bfloat16(q1);
        b.x = __float2bfloat16(q2); b.y = __float2bfloat16(q3);
        dst[2 * i] = a; dst[2 * i + 1] = b;
    }
}

// ---------------- kernel 3: split x into hi/lo bf16 ----------------
__global__ void split_kernel(const float4* __restrict__ x4, int n4) {
    __nv_bfloat162* hi2 = reinterpret_cast<__nv_bfloat162*>(g_xhi);
    __nv_bfloat162* lo2 = reinterpret_cast<__nv_bfloat162*>(g_xlo);
    for (int i = blockIdx.x * blockDim.x + threadIdx.x; i < n4; i += gridDim.x * blockDim.x) {
        float4 v = x4[i];
        __nv_bfloat16 hx = __float2bfloat16(v.x), hy = __float2bfloat16(v.y);
        __nv_bfloat16 hz = __float2bfloat16(v.z), hw = __float2bfloat16(v.w);
        __nv_bfloat162 h01, h23, l01, l23;
        h01.x = hx; h01.y = hy; h23.x = hz; h23.y = hw;
        l01.x = __float2bfloat16(v.x - __bfloat162float(hx));
        l01.y = __float2bfloat16(v.y - __bfloat162float(hy));
        l23.x = __float2bfloat16(v.z - __bfloat162float(hz));
        l23.y = __float2bfloat16(v.w - __bfloat162float(hw));
        hi2[2 * i] = h01; hi2[2 * i + 1] = h23;
        lo2[2 * i] = l01; lo2[2 * i + 1] = l23;
    }
}

// ---------------- kernel 4: HMMA GEMM  out = s_w*(xhi@W'^T + xlo@W'^T) + bias ----------------
// CTA tile 128x128, BK=32, 8 warps (2m x 4n), warp tile 64x32, 3-stage cp.async, 2 CTAs/SM.
// Prefetch issued AFTER the compute block (round-4 ordering — empirically fastest).
#define BM 128
#define BN 128
#define BK 32
#define PITCH 40                      // bf16 elements per smem row (80 B, conflict-free)
#define MAT_BYTES (128 * PITCH * 2)   // 10240 B per matrix
#define STAGE_BYTES (3 * MAT_BYTES)   // A_hi, A_lo, B
#define NSTAGE 3

__global__ __launch_bounds__(256, 2)
void gemm_tc(const float* __restrict__ bias, int IN, int OUT, int nPer) {
    extern __shared__ char dsm[];
    const uint32_t sb = smem_u32(dsm);
    const int t = threadIdx.x;
    const int wid = t >> 5;
    const int lane = t & 31;
    const int wm = wid & 1;           // 2 m-warps
    const int wn = wid >> 1;          // 4 n-warps
    const int mwarp = wm * 64;
    const int nwarp = wn * 32;
    const int rowbase = blockIdx.y * BM;
    const int colbase = blockIdx.x * BN;
    const int NITER = IN / BK;

    const __nv_bfloat16* xhi = g_xhi;
    const __nv_bfloat16* xlo = g_xlo;
    const __nv_bfloat16* wqb = g_wqb;

    // stage loader: 1536 x 16B chunks (A_hi 512, A_lo 512, B 512), 6 per thread
    auto load_stage = [&](int s, int it) {
        const int k0 = it * BK;
        const uint32_t st = sb + s * STAGE_BYTES;
        #pragma unroll
        for (int j = 0; j < 6; j++) {
            const int m = j >> 1;                 // 0: xhi, 1: xlo, 2: W'
            const int ci = ((j & 1) << 8) + t;    // 0..511
            const int r = ci >> 2, c = ci & 3;
            uint32_t dst = st + (uint32_t)(m * MAT_BYTES + r * (PITCH * 2) + c * 16);
            const __nv_bfloat16* src;
            if (m == 0)      src = xhi + (size_t)(rowbase + r) * IN + k0 + c * 8;
            else if (m == 1) src = xlo + (size_t)(rowbase + r) * IN + k0 + c * 8;
            else             src = wqb + (size_t)(colbase + r) * IN + k0 + c * 8;
            cpa16(dst, src);
        }
    };

    // ldmatrix per-thread address components
    const int rowA = lane & 15;                           // row within 16-row tile
    const int kcolA = (lane >> 4) << 3;                   // 0 or 8
    const int rowB = (lane & 7) + ((lane >> 4) & 1) * 8;  // row within 16-row pair of n-tiles
    const int kcolB = ((lane >> 3) & 1) << 3;             // 0 or 8

    float acc[4][4][4];
    #pragma unroll
    for (int i = 0; i < 4; i++)
        #pragma unroll
        for (int j = 0; j < 4; j++)
            #pragma unroll
            for (int e = 0; e < 4; e++) acc[i][j][e] = 0.0f;

    load_stage(0, 0); cpa_commit();
    load_stage(1, 1); cpa_commit();

    for (int it = 0; it < NITER; ++it) {
        const int s = it % NSTAGE;
        cpa_wait<1>();
        __syncthreads();
        const uint32_t st = sb + s * STAGE_BYTES;
        #pragma unroll
        for (int kk = 0; kk < 2; kk++) {
            const int kb = kk * 16;
            // B: 4 n-tiles via 2 paired ldmatrix.x4 (2 n-tiles each)
            uint32_t b[4][2];
            #pragma unroll
            for (int np = 0; np < 2; np++) {
                uint32_t addr = st + 2 * MAT_BYTES +
                    (uint32_t)((nwarp + np * 16 + rowB) * (PITCH * 2) + (kb + kcolB) * 2);
                ldsm_x4(b[2 * np][0], b[2 * np][1], b[2 * np + 1][0], b[2 * np + 1][1], addr);
            }
            uint32_t a[4][4];
            // hi
            #pragma unroll
            for (int mt = 0; mt < 4; mt++) {
                uint32_t addr = st +
                    (uint32_t)((mwarp + mt * 16 + rowA) * (PITCH * 2) + (kb + kcolA) * 2);
                ldsm_x4(a[mt][0], a[mt][1], a[mt][2], a[mt][3], addr);
            }
            #pragma unroll
            for (int mt = 0; mt < 4; mt++)
                #pragma unroll
                for (int nt = 0; nt < 4; nt++) mma16816(acc[mt][nt], a[mt], b[nt]);
            // lo
            #pragma unroll
            for (int mt = 0; mt < 4; mt++) {
                uint32_t addr = st + MAT_BYTES +
                    (uint32_t)((mwarp + mt * 16 + rowA) * (PITCH * 2) + (kb + kcolA) * 2);
                ldsm_x4(a[mt][0], a[mt][1], a[mt][2], a[mt][3], addr);
            }
            #pragma unroll
            for (int mt = 0; mt < 4; mt++)
                #pragma unroll
                for (int nt = 0; nt < 4; nt++) mma16816(acc[mt][nt], a[mt], b[nt]);
        }
        if (it + 2 < NITER) load_stage((it + 2) % NSTAGE, it + 2);
        cpa_commit();
    }

    // ---------------- epilogue ----------------
    const float s_w = g_sw;
    float lmn = INFINITY, lmx = -INFINITY;

    float2 bv[4];
    #pragma unroll
    for (int nt = 0; nt < 4; nt++)
        bv[nt] = *reinterpret_cast<const float2*>(bias + colbase + nwarp + nt * 8 + (lane & 3) * 2);

    #pragma unroll
    for (int mt = 0; mt < 4; mt++) {
        #pragma unroll
        for (int half = 0; half < 2; half++) {
            const int grow = rowbase + mwarp + mt * 16 + (lane >> 2) + half * 8;
            float* dstrow = g_out + (size_t)grow * OUT + colbase + nwarp + (lane & 3) * 2;
            #pragma unroll
            for (int nt = 0; nt < 4; nt++) {
                float v0 = fmaf(s_w, acc[mt][nt][half * 2 + 0], bv[nt].x);
                float v1 = fmaf(s_w, acc[mt][nt][half * 2 + 1], bv[nt].y);
                lmn = fminf(lmn, fminf(v0, v1));
                lmx = fmaxf(lmx, fmaxf(v0, v1));
                *reinterpret_cast<float2*>(dstrow + nt * 8) = make_float2(v0, v1);
            }
        }
    }

    #pragma unroll
    for (int o = 16; o; o >>= 1) {
        lmn = fminf(lmn, __shfl_xor_sync(0xffffffffu, lmn, o));
        lmx = fmaxf(lmx, __shfl_xor_sync(0xffffffffu, lmx, o));
    }
    __shared__ float rmn[8], rmx[8];
    if (lane == 0) { rmn[wid] = lmn; rmx[wid] = lmx; }
    __syncthreads();
    if (t == 0) {
        for (int i = 1; i < 8; i++) { lmn = fminf(lmn, rmn[i]); lmx = fmaxf(lmx, rmx[i]); }
        int cl = rowbase / nPer;
        atomicMin(&g_cmin[cl], f2o(lmn));
        atomicMax(&g_cmax[cl], f2o(lmx));
    }
}

// ---------------- kernel 5: EMA range update + qparams ----------------
__global__ void range_kernel(const float* __restrict__ act_range, const int* __restrict__ cinfo,
                             float* __restrict__ out_range, int K) {
    int t = threadIdx.x;
    if (t < K) {
        out_range[2 * t]     = act_range[2 * t];
        out_range[2 * t + 1] = act_range[2 * t + 1];
    }
    __syncthreads();
    if (t < K) {
        float mn = o2f(g_cmin[t]), mx = o2f(g_cmax[t]);
        int c = cinfo[2 * t];
        float o0 = act_range[2 * c], o1 = act_range[2 * c + 1];
        float nmin = __fadd_rn(__fmul_rn(o0, 0.999f), __fmul_rn(mn, 0.001f));
        float nmax = __fadd_rn(__fmul_rn(o1, 0.999f), __fmul_rn(mx, 0.001f));
        out_range[2 * c]     = nmin;
        out_range[2 * c + 1] = nmax;
        float s = __fdiv_rn(__fsub_rn(nmax, nmin), 255.0f);
        g_s3[t] = s;
        g_z3[t] = -rintf(__fdiv_rn(nmin, s));
    }
}

// ---------------- kernel 6: fake-quantize GEMM output ----------------
__global__ void quantout_kernel(float4* __restrict__ outq, int n4, int shift) {
    const float4* src = reinterpret_cast<const float4*>(g_out);
    for (int i = blockIdx.x * blockDim.x + threadIdx.x; i < n4; i += gridDim.x * blockDim.x) {
        int k = i >> shift;
        float s = g_s3[k], z = g_z3[k];
        float4 v = src[i];
        v.x = fq(v.x, s, z); v.y = fq(v.y, s, z);
        v.z = fq(v.z, s, z); v.w = fq(v.w, s, z);
        outq[i] = v;
    }
}
// fallback when chunk4 is not a power of two
__global__ void quantout_div_kernel(float4* __restrict__ outq, int n4, int chunk4) {
    const float4* src = reinterpret_cast<const float4*>(g_out);
    for (int i = blockIdx.x * blockDim.x + threadIdx.x; i < n4; i += gridDim.x * blockDim.x) {
        int k = i / chunk4;
        float s = g_s3[k], z = g_z3[k];
        float4 v = src[i];
        v.x = fq(v.x, s, z); v.y = fq(v.y, s, z);
        v.z = fq(v.z, s, z); v.w = fq(v.w, s, z);
        outq[i] = v;
    }
}

// ---------------- launch ----------------
extern "C" void kernel_launch(void* const* d_in, const int* in_sizes, int n_in,
                              void* d_out, int out_size) {
    const float* x         = (const float*)d_in[0];
    const float* w         = (const float*)d_in[1];
    const float* bias      = (const float*)d_in[2];
    const float* act_range = (const float*)d_in[3];
    const int*   cinfo     = (const int*)d_in[4];

    const int OUT = in_sizes[2];
    const int IN  = in_sizes[1] / OUT;
    const int B   = in_sizes[0] / IN;
    const int K   = in_sizes[3] / 2;
    const int n   = B / K;

    float* outq      = (float*)d_out;
    float* out_range = outq + (size_t)B * OUT;

    const int smem_bytes = NSTAGE * STAGE_BYTES;
    cudaFuncSetAttribute(gemm_tc, cudaFuncAttributeMaxDynamicSharedMemorySize, smem_bytes);

    init_kernel<<<1, 32>>>();

    const int wn4 = (OUT * IN) / 4;
    wminmax_kernel<<<512, 256>>>((const float4*)w, wn4);
    quantw_kernel<<<2048, 256>>>((const float4*)w, wn4);

    const int xn4 = (B * IN) / 4;
    split_kernel<<<2048, 256>>>((const float4*)x, xn4);

    dim3 grid(OUT / BN, B / BM);
    gemm_tc<<<grid, 256, smem_bytes>>>(bias, IN, OUT, n);

    range_kernel<<<1, 32>>>(act_range, cinfo, out_range, K);

    const int on4 = (B / 4) * OUT;
    const int chunk4 = (n * OUT) / 4;
    if ((chunk4 & (chunk4 - 1)) == 0) {
        int shift = 0;
        while ((1 << shift) < chunk4) shift++;
        quantout_kernel<<<2048, 256>>>((float4*)outq, on4, shift);
    } else {
        quantout_div_kernel<<<2048, 256>>>((float4*)outq, on4, chunk4);
    }
}

// round 12
// speedup vs baseline: 2.9591x; 1.0052x over previous
#include <cuda_runtime.h>
#include <cuda_bf16.h>
#include <math.h>
#include <stdint.h>

// ---------------- static scratch ----------------
static __device__ __nv_bfloat16 g_wqb[4096u * 4096u];   // W' = q - z (exact ints in bf16)
static __device__ __nv_bfloat16 g_xhi[10240u * 4096u];  // bf16 hi part of x
static __device__ __nv_bfloat16 g_xlo[10240u * 4096u];  // bf16 lo residual of x
static __device__ float g_out[10240u * 4096u];          // pre-quant GEMM output
__device__ unsigned g_wmm[2];
__device__ unsigned g_cmin[32], g_cmax[32];
__device__ float g_s3[32], g_z3[32];
__device__ float g_sw;

// ---- monotone float <-> uint encoding ----
__device__ __forceinline__ unsigned f2o(float f) {
    unsigned u = __float_as_uint(f);
    return (u & 0x80000000u) ? ~u : (u | 0x80000000u);
}
__device__ __forceinline__ float o2f(unsigned u) {
    unsigned v = (u & 0x80000000u) ? (u ^ 0x80000000u) : ~u;
    return __uint_as_float(v);
}
__device__ __forceinline__ float fq(float v, float s, float z) {
    float q = rintf(__fadd_rn(__fdiv_rn(v, s), z));
    q = fminf(fmaxf(q, 0.0f), 255.0f);
    return __fmul_rn(__fsub_rn(q, z), s);
}

// ---------------- PTX helpers ----------------
__device__ __forceinline__ uint32_t smem_u32(const void* p) {
    uint32_t a;
    asm("{ .reg .u64 t; cvta.to.shared.u64 t, %1; cvt.u32.u64 %0, t; }" : "=r"(a) : "l"(p));
    return a;
}
__device__ __forceinline__ void cpa16(uint32_t d, const void* s) {
    asm volatile("cp.async.cg.shared.global [%0], [%1], 16;" :: "r"(d), "l"(s));
}
__device__ __forceinline__ void cpa_commit() { asm volatile("cp.async.commit_group;" ::: "memory"); }
template<int N> __device__ __forceinline__ void cpa_wait() {
    asm volatile("cp.async.wait_group %0;" :: "n"(N) : "memory");
}
__device__ __forceinline__ void ldsm_x4(uint32_t& r0, uint32_t& r1, uint32_t& r2, uint32_t& r3,
                                        uint32_t addr) {
    asm volatile("ldmatrix.sync.aligned.m8n8.x4.shared.b16 {%0,%1,%2,%3}, [%4];"
                 : "=r"(r0), "=r"(r1), "=r"(r2), "=r"(r3) : "r"(addr));
}
__device__ __forceinline__ void mma16816(float* c, const uint32_t* a, const uint32_t* b) {
    asm volatile("mma.sync.aligned.m16n8k16.row.col.f32.bf16.bf16.f32 "
                 "{%0,%1,%2,%3}, {%4,%5,%6,%7}, {%8,%9}, {%0,%1,%2,%3};"
                 : "+f"(c[0]), "+f"(c[1]), "+f"(c[2]), "+f"(c[3])
                 : "r"(a[0]), "r"(a[1]), "r"(a[2]), "r"(a[3]), "r"(b[0]), "r"(b[1]));
}

// ---------------- kernel 0: reset reduction state ----------------
__global__ void init_kernel() {
    if (threadIdx.x == 0) { g_wmm[0] = 0xFFFFFFFFu; g_wmm[1] = 0u; }
    if (threadIdx.x < 32) { g_cmin[threadIdx.x] = 0xFFFFFFFFu; g_cmax[threadIdx.x] = 0u; }
}

// ---------------- kernel 1: weight min/max ----------------
__global__ void wminmax_kernel(const float4* __restrict__ w4, int n4) {
    float mn = INFINITY, mx = -INFINITY;
    for (int i = blockIdx.x * blockDim.x + threadIdx.x; i < n4; i += gridDim.x * blockDim.x) {
        float4 v = w4[i];
        mn = fminf(mn, fminf(fminf(v.x, v.y), fminf(v.z, v.w)));
        mx = fmaxf(mx, fmaxf(fmaxf(v.x, v.y), fmaxf(v.z, v.w)));
    }
    #pragma unroll
    for (int o = 16; o; o >>= 1) {
        mn = fminf(mn, __shfl_xor_sync(0xffffffffu, mn, o));
        mx = fmaxf(mx, __shfl_xor_sync(0xffffffffu, mx, o));
    }
    __shared__ float smn[8], smx[8];
    if ((threadIdx.x & 31) == 0) { smn[threadIdx.x >> 5] = mn; smx[threadIdx.x >> 5] = mx; }
    __syncthreads();
    if (threadIdx.x == 0) {
        for (int i = 1; i < (int)(blockDim.x >> 5); i++) { mn = fminf(mn, smn[i]); mx = fmaxf(mx, smx[i]); }
        atomicMin(&g_wmm[0], f2o(mn));
        atomicMax(&g_wmm[1], f2o(mx));
    }
}

// ---------------- kernel 2: W' = q - z into bf16 (exact) ----------------
__global__ void quantw_kernel(const float4* __restrict__ w4, int n4) {
    float mn = o2f(g_wmm[0]), mx = o2f(g_wmm[1]);
    float s = __fdiv_rn(__fsub_rn(mx, mn), 255.0f);
    float z = -rintf(__fdiv_rn(mn, s));
    if (blockIdx.x == 0 && threadIdx.x == 0) g_sw = s;
    __nv_bfloat162* dst = reinterpret_cast<__nv_bfloat162*>(g_wqb);
    for (int i = blockIdx.x * blockDim.x + threadIdx.x; i < n4; i += gridDim.x * blockDim.x) {
        float4 v = w4[i];
        float q0 = fminf(fmaxf(rintf(__fadd_rn(__fdiv_rn(v.x, s), z)), 0.f), 255.f) - z;
        float q1 = fminf(fmaxf(rintf(__fadd_rn(__fdiv_rn(v.y, s), z)), 0.f), 255.f) - z;
        float q2 = fminf(fmaxf(rintf(__fadd_rn(__fdiv_rn(v.z, s), z)), 0.f), 255.f) - z;
        float q3 = fminf(fmaxf(rintf(__fadd_rn(__fdiv_rn(v.w, s), z)), 0.f), 255.f) - z;
        __nv_bfloat162 a, b;
        a.x = __float2bfloat16(q0); a.y = __float2bfloat16(q1);
        b.x = __float2bfloat16(q2); b.y = __float2bfloat16(q3);
        dst[2 * i] = a; dst[2 * i + 1] = b;
    }
}

// ---------------- kernel 3: split x into hi/lo bf16 ----------------
__global__ void split_kernel(const float4* __restrict__ x4, int n4) {
    __nv_bfloat162* hi2 = reinterpret_cast<__nv_bfloat162*>(g_xhi);
    __nv_bfloat162* lo2 = reinterpret_cast<__nv_bfloat162*>(g_xlo);
    for (int i = blockIdx.x * blockDim.x + threadIdx.x; i < n4; i += gridDim.x * blockDim.x) {
        float4 v = x4[i];
        __nv_bfloat16 hx = __float2bfloat16(v.x), hy = __float2bfloat16(v.y);
        __nv_bfloat16 hz = __float2bfloat16(v.z), hw = __float2bfloat16(v.w);
        __nv_bfloat162 h01, h23, l01, l23;
        h01.x = hx; h01.y = hy; h23.x = hz; h23.y = hw;
        l01.x = __float2bfloat16(v.x - __bfloat162float(hx));
        l01.y = __float2bfloat16(v.y - __bfloat162float(hy));
        l23.x = __float2bfloat16(v.z - __bfloat162float(hz));
        l23.y = __float2bfloat16(v.w - __bfloat162float(hw));
        hi2[2 * i] = h01; hi2[2 * i + 1] = h23;
        lo2[2 * i] = l01; lo2[2 * i + 1] = l23;
    }
}

// ---------------- kernel 4: HMMA GEMM  out = s_w*(xhi@W'^T + xlo@W'^T) + bias ----------------
// CTA tile 128x128, BK=32, 8 warps (4m x 2n), warp tile 32x64, 3-stage cp.async,
// 2 CTAs/SM, prefetch AFTER compute (empirically fastest ordering).
#define BM 128
#define BN 128
#define BK 32
#define PITCH 40                      // bf16 elements per smem row (80 B, conflict-free)
#define MAT_BYTES (128 * PITCH * 2)   // 10240 B per matrix
#define STAGE_BYTES (3 * MAT_BYTES)   // A_hi, A_lo, B
#define NSTAGE 3

__global__ __launch_bounds__(256, 2)
void gemm_tc(const float* __restrict__ bias, int IN, int OUT, int nPer) {
    extern __shared__ char dsm[];
    const uint32_t sb = smem_u32(dsm);
    const int t = threadIdx.x;
    const int wid = t >> 5;
    const int lane = t & 31;
    const int wm = wid & 3;            // 4 m-warps
    const int wn = wid >> 2;           // 2 n-warps
    const int mwarp = wm * 32;
    const int nwarp = wn * 64;
    const int rowbase = blockIdx.y * BM;
    const int colbase = blockIdx.x * BN;
    const int NITER = IN / BK;

    const __nv_bfloat16* xhi = g_xhi;
    const __nv_bfloat16* xlo = g_xlo;
    const __nv_bfloat16* wqb = g_wqb;

    // stage loader: 1536 x 16B chunks (A_hi 512, A_lo 512, B 512), 6 per thread
    auto load_stage = [&](int s, int it) {
        const int k0 = it * BK;
        const uint32_t st = sb + s * STAGE_BYTES;
        #pragma unroll
        for (int j = 0; j < 6; j++) {
            const int m = j >> 1;                 // 0: xhi, 1: xlo, 2: W'
            const int ci = ((j & 1) << 8) + t;    // 0..511
            const int r = ci >> 2, c = ci & 3;
            uint32_t dst = st + (uint32_t)(m * MAT_BYTES + r * (PITCH * 2) + c * 16);
            const __nv_bfloat16* src;
            if (m == 0)      src = xhi + (size_t)(rowbase + r) * IN + k0 + c * 8;
            else if (m == 1) src = xlo + (size_t)(rowbase + r) * IN + k0 + c * 8;
            else             src = wqb + (size_t)(colbase + r) * IN + k0 + c * 8;
            cpa16(dst, src);
        }
    };

    // ldmatrix per-thread address components
    const int rowA = lane & 15;                           // row within 16-row tile
    const int kcolA = (lane >> 4) << 3;                   // 0 or 8
    const int rowB = (lane & 7) + ((lane >> 4) & 1) * 8;  // row within 16-row pair of n-tiles
    const int kcolB = ((lane >> 3) & 1) << 3;             // 0 or 8

    float acc[2][8][4];
    #pragma unroll
    for (int i = 0; i < 2; i++)
        #pragma unroll
        for (int j = 0; j < 8; j++)
            #pragma unroll
            for (int e = 0; e < 4; e++) acc[i][j][e] = 0.0f;

    load_stage(0, 0); cpa_commit();
    load_stage(1, 1); cpa_commit();

    for (int it = 0; it < NITER; ++it) {
        const int s = it % NSTAGE;
        cpa_wait<1>();
        __syncthreads();
        const uint32_t st = sb + s * STAGE_BYTES;
        #pragma unroll
        for (int kk = 0; kk < 2; kk++) {
            const int kb = kk * 16;
            // B: 8 n-tiles via 4 paired ldmatrix.x4 (2 n-tiles each)
            uint32_t b[8][2];
            #pragma unroll
            for (int np = 0; np < 4; np++) {
                uint32_t addr = st + 2 * MAT_BYTES +
                    (uint32_t)((nwarp + np * 16 + rowB) * (PITCH * 2) + (kb + kcolB) * 2);
                ldsm_x4(b[2 * np][0], b[2 * np][1], b[2 * np + 1][0], b[2 * np + 1][1], addr);
            }
            uint32_t a[2][4];
            // hi
            #pragma unroll
            for (int mt = 0; mt < 2; mt++) {
                uint32_t addr = st +
                    (uint32_t)((mwarp + mt * 16 + rowA) * (PITCH * 2) + (kb + kcolA) * 2);
                ldsm_x4(a[mt][0], a[mt][1], a[mt][2], a[mt][3], addr);
            }
            #pragma unroll
            for (int mt = 0; mt < 2; mt++)
                #pragma unroll
                for (int nt = 0; nt < 8; nt++) mma16816(acc[mt][nt], a[mt], b[nt]);
            // lo
            #pragma unroll
            for (int mt = 0; mt < 2; mt++) {
                uint32_t addr = st + MAT_BYTES +
                    (uint32_t)((mwarp + mt * 16 + rowA) * (PITCH * 2) + (kb + kcolA) * 2);
                ldsm_x4(a[mt][0], a[mt][1], a[mt][2], a[mt][3], addr);
            }
            #pragma unroll
            for (int mt = 0; mt < 2; mt++)
                #pragma unroll
                for (int nt = 0; nt < 8; nt++) mma16816(acc[mt][nt], a[mt], b[nt]);
        }
        if (it + 2 < NITER) load_stage((it + 2) % NSTAGE, it + 2);
        cpa_commit();
    }

    // ---------------- epilogue ----------------
    const float s_w = g_sw;
    float lmn = INFINITY, lmx = -INFINITY;

    float2 bv[8];
    #pragma unroll
    for (int nt = 0; nt < 8; nt++)
        bv[nt] = *reinterpret_cast<const float2*>(bias + colbase + nwarp + nt * 8 + (lane & 3) * 2);

    #pragma unroll
    for (int mt = 0; mt < 2; mt++) {
        #pragma unroll
        for (int half = 0; half < 2; half++) {
            const int grow = rowbase + mwarp + mt * 16 + (lane >> 2) + half * 8;
            float* dstrow = g_out + (size_t)grow * OUT + colbase + nwarp + (lane & 3) * 2;
            #pragma unroll
            for (int nt = 0; nt < 8; nt++) {
                float v0 = fmaf(s_w, acc[mt][nt][half * 2 + 0], bv[nt].x);
                float v1 = fmaf(s_w, acc[mt][nt][half * 2 + 1], bv[nt].y);
                lmn = fminf(lmn, fminf(v0, v1));
                lmx = fmaxf(lmx, fmaxf(v0, v1));
                *reinterpret_cast<float2*>(dstrow + nt * 8) = make_float2(v0, v1);
            }
        }
    }

    #pragma unroll
    for (int o = 16; o; o >>= 1) {
        lmn = fminf(lmn, __shfl_xor_sync(0xffffffffu, lmn, o));
        lmx = fmaxf(lmx, __shfl_xor_sync(0xffffffffu, lmx, o));
    }
    __shared__ float rmn[8], rmx[8];
    if (lane == 0) { rmn[wid] = lmn; rmx[wid] = lmx; }
    __syncthreads();
    if (t == 0) {
        for (int i = 1; i < 8; i++) { lmn = fminf(lmn, rmn[i]); lmx = fmaxf(lmx, rmx[i]); }
        int cl = rowbase / nPer;
        atomicMin(&g_cmin[cl], f2o(lmn));
        atomicMax(&g_cmax[cl], f2o(lmx));
    }
}

// ---------------- kernel 5: EMA range update + qparams ----------------
__global__ void range_kernel(const float* __restrict__ act_range, const int* __restrict__ cinfo,
                             float* __restrict__ out_range, int K) {
    int t = threadIdx.x;
    if (t < K) {
        out_range[2 * t]     = act_range[2 * t];
        out_range[2 * t + 1] = act_range[2 * t + 1];
    }
    __syncthreads();
    if (t < K) {
        float mn = o2f(g_cmin[t]), mx = o2f(g_cmax[t]);
        int c = cinfo[2 * t];
        float o0 = act_range[2 * c], o1 = act_range[2 * c + 1];
        float nmin = __fadd_rn(__fmul_rn(o0, 0.999f), __fmul_rn(mn, 0.001f));
        float nmax = __fadd_rn(__fmul_rn(o1, 0.999f), __fmul_rn(mx, 0.001f));
        out_range[2 * c]     = nmin;
        out_range[2 * c + 1] = nmax;
        float s = __fdiv_rn(__fsub_rn(nmax, nmin), 255.0f);
        g_s3[t] = s;
        g_z3[t] = -rintf(__fdiv_rn(nmin, s));
    }
}

// ---------------- kernel 6: fake-quantize GEMM output ----------------
__global__ void quantout_kernel(float4* __restrict__ outq, int n4, int shift) {
    const float4* src = reinterpret_cast<const float4*>(g_out);
    for (int i = blockIdx.x * blockDim.x + threadIdx.x; i < n4; i += gridDim.x * blockDim.x) {
        int k = i >> shift;
        float s = g_s3[k], z = g_z3[k];
        float4 v = src[i];
        v.x = fq(v.x, s, z); v.y = fq(v.y, s, z);
        v.z = fq(v.z, s, z); v.w = fq(v.w, s, z);
        outq[i] = v;
    }
}
// fallback when chunk4 is not a power of two
__global__ void quantout_div_kernel(float4* __restrict__ outq, int n4, int chunk4) {
    const float4* src = reinterpret_cast<const float4*>(g_out);
    for (int i = blockIdx.x * blockDim.x + threadIdx.x; i < n4; i += gridDim.x * blockDim.x) {
        int k = i / chunk4;
        float s = g_s3[k], z = g_z3[k];
        float4 v = src[i];
        v.x = fq(v.x, s, z); v.y = fq(v.y, s, z);
        v.z = fq(v.z, s, z); v.w = fq(v.w, s, z);
        outq[i] = v;
    }
}

// ---------------- launch ----------------
extern "C" void kernel_launch(void* const* d_in, const int* in_sizes, int n_in,
                              void* d_out, int out_size) {
    const float* x         = (const float*)d_in[0];
    const float* w         = (const float*)d_in[1];
    const float* bias      = (const float*)d_in[2];
    const float* act_range = (const float*)d_in[3];
    const int*   cinfo     = (const int*)d_in[4];

    const int OUT = in_sizes[2];
    const int IN  = in_sizes[1] / OUT;
    const int B   = in_sizes[0] / IN;
    const int K   = in_sizes[3] / 2;
    const int n   = B / K;

    float* outq      = (float*)d_out;
    float* out_range = outq + (size_t)B * OUT;

    const int smem_bytes = NSTAGE * STAGE_BYTES;
    cudaFuncSetAttribute(gemm_tc, cudaFuncAttributeMaxDynamicSharedMemorySize, smem_bytes);

    init_kernel<<<1, 32>>>();

    const int wn4 = (OUT * IN) / 4;
    wminmax_kernel<<<512, 256>>>((const float4*)w, wn4);
    quantw_kernel<<<2048, 256>>>((const float4*)w, wn4);

    const int xn4 = (B * IN) / 4;
    split_kernel<<<2048, 256>>>((const float4*)x, xn4);

    dim3 grid(OUT / BN, B / BM);
    gemm_tc<<<grid, 256, smem_bytes>>>(bias, IN, OUT, n);

    range_kernel<<<1, 32>>>(act_range, cinfo, out_range, K);

    const int on4 = (B / 4) * OUT;
    const int chunk4 = (n * OUT) / 4;
    if ((chunk4 & (chunk4 - 1)) == 0) {
        int shift = 0;
        while ((1 << shift) < chunk4) shift++;
        quantout_kernel<<<2048, 256>>>((float4*)outq, on4, shift);
    } else {
        quantout_div_kernel<<<2048, 256>>>((float4*)outq, on4, chunk4);
    }
}